// round 7
// baseline (speedup 1.0000x reference)
#include <cuda_runtime.h>
#include <cuda_fp16.h>
#include <mma.h>
#include <cstdint>
using namespace nvcuda;

#define NN 50000
#define NE 500000
#define LDA 136
#define LDC 132

__device__ float g_agg[(size_t)NN * 128];
// fp16 weight images [grp][k][o*128+i]; grp: 0=W1(x_i) 1=W1(x_j) 2=W2 3=W3(x) 4=W3(agg) 5=W4
__device__ __align__(16) __half g_W16[6][8][16384];

__device__ __forceinline__ float swishf(float v) { return __fdividef(v, 1.0f + __expf(-v)); }

__global__ void k_zero() {
    int i = blockIdx.x * blockDim.x + threadIdx.x;
    for (; i < NN * 128; i += gridDim.x * blockDim.x) g_agg[i] = 0.0f;
}

__global__ void k_prep(const float* __restrict__ W1, const float* __restrict__ W2,
                       const float* __restrict__ W3, const float* __restrict__ W4) {
    const int grp = blockIdx.x >> 3, k = blockIdx.x & 7;
    const float* W; int ioff = 0;
    switch (grp) {
        case 0: W = W1; break;
        case 1: W = W1; ioff = 128; break;
        case 2: W = W2; break;
        case 3: W = W3; break;
        case 4: W = W3; ioff = 128; break;
        default: W = W4; break;
    }
    for (int idx = threadIdx.x; idx < 16384; idx += blockDim.x) {
        const int o = idx >> 7, i = idx & 127;
        g_W16[grp][k][idx] = __float2half_rn(W[(size_t)(ioff + i) * 1024 + k * 128 + o]);
    }
}

// smem byte offsets
#define OFF_ATTR 0
#define OFF_EXT  4096
#define OFF_IDX  5632
#define OFF_BIAS 6656
#define OFF_WC   7680
#define OFF_A0   20480
#define OFF_A1   55296
#define OFF_B0   90112
#define OFF_B1   124928
#define OFF_B2   159744
#define SMEM_SZ  194560

// MODE 0: edges (rows=edges, gather x[dst]/x[src], scatter to g_agg)
// MODE 1: nodes (rows=nodes, x then g_agg, store out)
template <int MODE>
__global__ void __launch_bounds__(512, 1) k_main(
    const int* __restrict__ eidx, const float* __restrict__ attr,
    const float* __restrict__ ext, const float* __restrict__ x,
    const float* __restrict__ wcs, const float* __restrict__ bA,
    const float* __restrict__ bB, float* __restrict__ outp)
{
    extern __shared__ unsigned char sm[];
    float* s_attr = (float*)sm;
    float* s_ext  = (float*)(sm + OFF_EXT);
    int*   s_idx  = (int*)(sm + OFF_IDX);
    float* s_bias = (float*)(sm + OFF_BIAS);
    float* s_wc   = (float*)(sm + OFF_WC);
    __half* sA[2] = {(__half*)(sm + OFF_A0), (__half*)(sm + OFF_A1)};
    const __half* sB[3] = {(const __half*)(sm + OFF_B0), (const __half*)(sm + OFF_B1),
                           (const __half*)(sm + OFF_B2)};
    float* sC = (float*)(sm + OFF_A0);   // alias: live only at g==16 and after the loop
    uint32_t sbB[3];
    asm("{ .reg .u64 t; cvta.to.shared.u64 t, %1; cvt.u32.u64 %0, t; }" : "=r"(sbB[0]) : "l"(sm + OFF_B0));
    asm("{ .reg .u64 t; cvta.to.shared.u64 t, %1; cvt.u32.u64 %0, t; }" : "=r"(sbB[1]) : "l"(sm + OFF_B1));
    asm("{ .reg .u64 t; cvta.to.shared.u64 t, %1; cvt.u32.u64 %0, t; }" : "=r"(sbB[2]) : "l"(sm + OFF_B2));

    const int tid = threadIdx.x, wid = tid >> 5;
    const int r = tid >> 2, c0 = (tid & 3) * 32;   // 4 threads per row, 32 cols each
    const int t0 = blockIdx.x * 128;
    const int NROW = MODE ? NN : NE;
    const int wg0 = MODE ? 3 : 0;
    const int wr = (wid & 3) * 32, wc = (wid >> 2) * 32;

    for (int i = tid; i < 1024; i += 512) { int gi = t0 * 8 + i; s_attr[i] = (gi < NROW * 8) ? attr[gi] : 0.f; }
    for (int i = tid; i < 384; i += 512)  { int gi = t0 * 3 + i; s_ext[i]  = (gi < NROW * 3) ? ext[gi]  : 0.f; }
    if (tid < 128) {
        s_bias[tid] = bA[tid]; s_bias[128 + tid] = bB[tid];
        if (!MODE) {
            const int e = t0 + tid;
            s_idx[tid]       = (e < NE) ? eidx[e]      : 0;   // src
            s_idx[128 + tid] = (e < NE) ? eidx[NE + e] : 0;   // dst
        }
    }
    for (int i = tid; i < 3072; i += 512) s_wc[i] = wcs[i];
    __syncthreads();

    int rowA;
    if (MODE) { const int gn = t0 + r; rowA = (gn < NN) ? gn : NN - 1; }
    else rowA = s_idx[128 + r];

    float rrow[32];
    {
        const float4* p = (const float4*)(x + (size_t)rowA * 128 + c0);
#pragma unroll
        for (int j = 0; j < 8; j++) {
            float4 v = p[j];
            rrow[4*j] = v.x; rrow[4*j+1] = v.y; rrow[4*j+2] = v.z; rrow[4*j+3] = v.w;
        }
    }

    // prefetch B(0), B(1)
#pragma unroll
    for (int pg = 0; pg < 2; pg++) {
        const char* src = (const char*)g_W16[wg0][pg];
#pragma unroll
        for (int it = 0; it < 4; it++) {
            const int idx = tid + it * 512, o = idx >> 4, c = idx & 15;
            asm volatile("cp.async.cg.shared.global [%0], [%1], 16;"
                         :: "r"(sbB[pg] + (uint32_t)(o * 272 + c * 16)), "l"(src + o * 256 + c * 16));
        }
        asm volatile("cp.async.commit_group;" ::: "memory");
    }

    wmma::fragment<wmma::accumulator, 16, 16, 16, float> acc[2][2];
#pragma unroll
    for (int m = 0; m < 2; m++)
#pragma unroll
        for (int n = 0; n < 2; n++) wmma::fill_fragment(acc[m][n], 0.f);

#pragma unroll 1
    for (int g = 0; g < 24; g++) {
        if (g == 8) {  // switch row source: x[src] (edges) / g_agg (nodes)
            const float* base = MODE ? ((const float*)g_agg + (size_t)rowA * 128)
                                     : (x + (size_t)s_idx[r] * 128);
            const float4* p = (const float4*)(base + c0);
#pragma unroll
            for (int j = 0; j < 8; j++) {
                float4 v = p[j];
                rrow[4*j] = v.x; rrow[4*j+1] = v.y; rrow[4*j+2] = v.z; rrow[4*j+3] = v.w;
            }
        }
        if (g == 16) {  // epilogue 1: rows = swish(C + bA + ext-rows term); C aliases A
            __syncthreads();  // all mma(15) reads of sA done before overwriting with C
#pragma unroll
            for (int m = 0; m < 2; m++)
#pragma unroll
                for (int n = 0; n < 2; n++)
                    wmma::store_matrix_sync(sC + (wr + 16*m) * LDC + wc + 16*n, acc[m][n], LDC, wmma::mem_row_major);
            __syncthreads();
            float p24[24];
#pragma unroll
            for (int i = 0; i < 3; i++)
#pragma unroll
                for (int k2 = 0; k2 < 8; k2++) p24[i * 8 + k2] = s_ext[r * 3 + i] * s_attr[r * 8 + k2];
#pragma unroll
            for (int j4 = 0; j4 < 8; j4++) {
                float4 t = *(float4*)(sC + r * LDC + c0 + j4 * 4);
#pragma unroll
                for (int q = 0; q < 24; q++) {
                    float4 wv = *(const float4*)(s_wc + q * 128 + c0 + j4 * 4);
                    t.x = fmaf(p24[q], wv.x, t.x); t.y = fmaf(p24[q], wv.y, t.y);
                    t.z = fmaf(p24[q], wv.z, t.z); t.w = fmaf(p24[q], wv.w, t.w);
                }
                float4 bv = *(const float4*)(s_bias + c0 + j4 * 4);
                rrow[4*j4]   = swishf(t.x + bv.x); rrow[4*j4+1] = swishf(t.y + bv.y);
                rrow[4*j4+2] = swishf(t.z + bv.z); rrow[4*j4+3] = swishf(t.w + bv.w);
            }
#pragma unroll
            for (int m = 0; m < 2; m++)
#pragma unroll
                for (int n = 0; n < 2; n++) wmma::fill_fragment(acc[m][n], 0.f);
            __syncthreads();  // all sC reads done before A(16) build overwrites alias
        }
        // build A(g) = attr_k * rrow  (fp16)
        {
            const float sc = s_attr[r * 8 + (g & 7)];
            __half2* dst = (__half2*)(sA[g & 1] + r * LDA + c0);
#pragma unroll
            for (int j = 0; j < 16; j++)
                dst[j] = __floats2half2_rn(rrow[2*j] * sc, rrow[2*j+1] * sc);
        }
        if (g < 23) asm volatile("cp.async.wait_group 1;" ::: "memory");
        else        asm volatile("cp.async.wait_group 0;" ::: "memory");
        __syncthreads();
        if (g < 22) {  // prefetch B(g+2) into ring slot (g+2)%3
            const int ng = g + 2;
            const char* src = (const char*)g_W16[wg0 + (ng >> 3)][ng & 7];
            const uint32_t db = sbB[ng % 3];
#pragma unroll
            for (int it = 0; it < 4; it++) {
                const int idx = tid + it * 512, o = idx >> 4, c = idx & 15;
                asm volatile("cp.async.cg.shared.global [%0], [%1], 16;"
                             :: "r"(db + (uint32_t)(o * 272 + c * 16)), "l"(src + o * 256 + c * 16));
            }
            asm volatile("cp.async.commit_group;" ::: "memory");
        }
        // mma over 8 k-steps (warp tile 32x32)
        {
            const __half* Ab = sA[g & 1];
            const __half* Bb = sB[g % 3];
#pragma unroll
            for (int ks = 0; ks < 8; ks++) {
                wmma::fragment<wmma::matrix_a, 16, 16, 16, __half, wmma::row_major> fa0, fa1;
                wmma::load_matrix_sync(fa0, Ab + (size_t)wr * LDA + ks * 16, LDA);
                wmma::load_matrix_sync(fa1, Ab + (size_t)(wr + 16) * LDA + ks * 16, LDA);
#pragma unroll
                for (int n = 0; n < 2; n++) {
                    wmma::fragment<wmma::matrix_b, 16, 16, 16, __half, wmma::col_major> fb;
                    wmma::load_matrix_sync(fb, Bb + (size_t)(wc + 16 * n) * LDA + ks * 16, LDA);
                    wmma::mma_sync(acc[0][n], fa0, fb, acc[0][n]);
                    wmma::mma_sync(acc[1][n], fa1, fb, acc[1][n]);
                }
            }
        }
    }

    // final epilogue (C aliases A again)
    __syncthreads();
#pragma unroll
    for (int m = 0; m < 2; m++)
#pragma unroll
        for (int n = 0; n < 2; n++)
            wmma::store_matrix_sync(sC + (wr + 16*m) * LDC + wc + 16*n, acc[m][n], LDC, wmma::mem_row_major);
    __syncthreads();
    if (t0 + r < NROW) {
        if (MODE) {
            float* op = outp + (size_t)(t0 + r) * 128 + c0;
#pragma unroll
            for (int j4 = 0; j4 < 8; j4++) {
                float4 t = *(float4*)(sC + r * LDC + c0 + j4 * 4);
                float4 bv = *(const float4*)(s_bias + 128 + c0 + j4 * 4);
                *(float4*)(op + j4 * 4) = make_float4(t.x + bv.x, t.y + bv.y, t.z + bv.z, t.w + bv.w);
            }
        } else {
            float* ap = g_agg + (size_t)rowA * 128 + c0;
#pragma unroll
            for (int j4 = 0; j4 < 8; j4++) {
                float4 t = *(float4*)(sC + r * LDC + c0 + j4 * 4);
                float4 bv = *(const float4*)(s_bias + 128 + c0 + j4 * 4);
                float vx = swishf(t.x + bv.x), vy = swishf(t.y + bv.y);
                float vz = swishf(t.z + bv.z), vw = swishf(t.w + bv.w);
                asm volatile("red.global.add.v4.f32 [%0], {%1, %2, %3, %4};"
                             :: "l"(ap + j4 * 4), "f"(vx), "f"(vy), "f"(vz), "f"(vw)
                             : "memory");
            }
        }
    }
}

extern "C" void kernel_launch(void* const* d_in, const int* in_sizes, int n_in,
                              void* d_out, int out_size) {
    const float *x = nullptr, *ea = nullptr, *na = nullptr, *amf = nullptr, *anf = nullptr;
    const float *W1 = nullptr, *b1 = nullptr, *W2 = nullptr, *b2 = nullptr;
    const float *W3 = nullptr, *b3 = nullptr, *W4 = nullptr, *b4 = nullptr;
    const int* eidx = nullptr;
    for (int i = 0; i < n_in; i++) {
        switch (in_sizes[i]) {
            case 6400000: x   = (const float*)d_in[i]; break;
            case 1000000: eidx = (const int*)d_in[i]; break;
            case 4000000: ea  = (const float*)d_in[i]; break;
            case 400000:  na  = (const float*)d_in[i]; break;
            case 1500000: amf = (const float*)d_in[i]; break;
            case 150000:  anf = (const float*)d_in[i]; break;
            case 265216:  if (!W1) W1 = (const float*)d_in[i]; else W3 = (const float*)d_in[i]; break;
            case 131072:  if (!W2) W2 = (const float*)d_in[i]; else W4 = (const float*)d_in[i]; break;
            case 128:
                if (!b1) b1 = (const float*)d_in[i];
                else if (!b2) b2 = (const float*)d_in[i];
                else if (!b3) b3 = (const float*)d_in[i];
                else b4 = (const float*)d_in[i];
                break;
            default: break;
        }
    }

    cudaFuncSetAttribute(k_main<0>, cudaFuncAttributeMaxDynamicSharedMemorySize, SMEM_SZ);
    cudaFuncSetAttribute(k_main<1>, cudaFuncAttributeMaxDynamicSharedMemorySize, SMEM_SZ);

    k_prep<<<48, 256>>>(W1, W2, W3, W4);
    k_zero<<<6400, 512>>>();
    k_main<0><<<3907, 512, SMEM_SZ>>>(eidx, ea, amf, x, W1 + 256 * 1024, b1, b2, nullptr);
    k_main<1><<<391, 512, SMEM_SZ>>>(eidx, na, anf, x, W3 + 256 * 1024, b3, b4, (float*)d_out);
}